// round 15
// baseline (speedup 1.0000x reference)
#include <cuda_runtime.h>
#include <cuda_fp16.h>
#include <mma.h>
#include <cstdint>

using namespace nvcuda;

// Problem constants
#define MROWS 100000
#define FDIM  256
#define DDIM  128
#define NHOP  3
#define NE    1600000
#define NCOLS 512              // 3*128 fw blocks + 128 baseline block
#define MB    782              // ceil(100000/128)
#define SCANB 98               // ceil(100000/1024)

// ---------------------------------------------------------------------------
// Device scratch
// ---------------------------------------------------------------------------
__device__ __half  g_fw[(size_t)NHOP * MROWS * DDIM];   // per-hop fw (fp16)
__device__ __half  g_Xf[(size_t)MROWS * FDIM];          // X fp16
__device__ __half  g_Wtf[(size_t)NCOLS * FDIM];         // Wcomb^T fp16 [512][256]
__device__ int     g_rowptr[NHOP * MROWS];
__device__ int     g_cur[NHOP * MROWS];
__device__ int     g_aux[NHOP * 128];
__device__ int2    g_ecv[(size_t)NHOP * NE];            // CSR-ordered {col, val}

__device__ __forceinline__ uint32_t smem_u32(const void* p) {
    uint32_t a;
    asm("{ .reg .u64 t; cvta.to.shared.u64 t, %1; cvt.u32.u64 %0, t; }" : "=r"(a) : "l"(p));
    return a;
}
__device__ __forceinline__ void cp16(uint32_t dst, const void* src, int src_sz) {
    asm volatile("cp.async.ca.shared.global [%0], [%1], 16, %2;"
                 :: "r"(dst), "l"(src), "r"(src_sz) : "memory");
}

// ---------------------------------------------------------------------------
// Convert X (fp32) -> fp16
// ---------------------------------------------------------------------------
__global__ void convert_kernel(const float* __restrict__ X)
{
    size_t i = (size_t)blockIdx.x * blockDim.x + threadIdx.x;
    const size_t total4 = (size_t)MROWS * FDIM / 4;
    if (i >= total4) return;
    float4 v = ((const float4*)X)[i];
    __half2 a = __floats2half2_rn(v.x, v.y);
    __half2 b = __floats2half2_rn(v.z, v.w);
    ((uint2*)g_Xf)[i] = make_uint2(*(uint32_t*)&a, *(uint32_t*)&b);
}

// ---------------------------------------------------------------------------
// Fold kernel: build Wcomb^T in fp16.  grid=256 (k), block=512 (j)
// ---------------------------------------------------------------------------
__global__ void fold_kernel(const float* __restrict__ W_embed,
                            const float* __restrict__ W_feat,
                            const float* __restrict__ W_embK,
                            const float* __restrict__ alpha_p)
{
    int k = blockIdx.x;
    int j = threadIdx.x;
    float r;
    if (j < 3 * DDIM) {
        int hop = j >> 7;
        int jj  = j & 127;
        r = W_feat[((size_t)hop * FDIM + k) * DDIM + jj];
    } else {
        int jj = j - 3 * DDIM;
        float s = 0.f;
        #pragma unroll 4
        for (int d = 0; d < DDIM; d++) {
            float wc = W_embK[d * DDIM + jj]
                     + W_embK[DDIM * DDIM + d * DDIM + jj]
                     + W_embK[2 * DDIM * DDIM + d * DDIM + jj];
            s += W_embed[k * DDIM + d] * wc;
        }
        r = alpha_p[0] * s;
    }
    g_Wtf[(size_t)j * FDIM + k] = __float2half_rn(r);
}

// ---------------------------------------------------------------------------
// Single-pass fp16 wmma GEMM with cp.async double buffering.
// grid = (4 N-blocks, 782 M-blocks), 256 threads, 128x128 CTA tile, BK=32.
// ROWH=40 (80B row stride): ldmatrix rows hit 8 distinct 16B bank slots
// (80*r mod 128 = 0,80,32,112,64,16,96,48) -> conflict-free fragment loads.
// Dynamic smem: 2 stages x 2 tiles x (128 x 40 halves) = 40960 bytes.
// ---------------------------------------------------------------------------
#define ROWH    40
#define TILE_H  (128 * ROWH)
#define STAGE_H (2 * TILE_H)
#define STAGE_B (STAGE_H * 2)            // 20480 bytes
#define NKC     8

__global__ void __launch_bounds__(256, 3)
mm_kernel(float* __restrict__ outp)
{
    extern __shared__ __align__(32) __half smem[];
    const uint32_t sb = smem_u32(smem);

    int tid  = threadIdx.x;
    int wid  = tid >> 5;
    int lane = tid & 31;
    int nb   = blockIdx.x;
    int mb   = blockIdx.y;
    int row0 = mb * 128;
    int n0   = nb * 128;
    int warp_m = (wid & 1) * 64;
    int warp_n = (wid >> 1) * 32;

    auto issue_stage = [&](int kc, int stage) {
        const int k0 = kc * 32;
        const uint32_t s0 = sb + stage * STAGE_B;
        #pragma unroll
        for (int t = 0; t < 2; t++) {
            int c   = tid + 256 * t;
            int row = c >> 2;
            int c4  = c & 3;
            uint32_t doff = (uint32_t)(row * ROWH + c4 * 8) * 2;
            int gr = row0 + row;
            int ok = (gr < MROWS) ? 16 : 0;
            cp16(s0 + doff, g_Xf + (size_t)gr * FDIM + k0 + c4 * 8, ok);
            cp16(s0 + TILE_H * 2 + doff, g_Wtf + (size_t)(n0 + row) * FDIM + k0 + c4 * 8, 16);
        }
        asm volatile("cp.async.commit_group;" ::: "memory");
    };

    wmma::fragment<wmma::accumulator, 16, 16, 16, float> acc[4][2];
    #pragma unroll
    for (int i = 0; i < 4; i++)
        #pragma unroll
        for (int j = 0; j < 2; j++)
            wmma::fill_fragment(acc[i][j], 0.f);

    issue_stage(0, 0);

    for (int kc = 0; kc < NKC; kc++) {
        int stage = kc & 1;
        if (kc + 1 < NKC) {
            issue_stage(kc + 1, stage ^ 1);
            asm volatile("cp.async.wait_group 1;" ::: "memory");
        } else {
            asm volatile("cp.async.wait_group 0;" ::: "memory");
        }
        __syncthreads();

        __half* sA = smem + stage * STAGE_H;
        __half* sB = sA + TILE_H;

        #pragma unroll
        for (int s = 0; s < 2; s++) {
            wmma::fragment<wmma::matrix_b, 16, 16, 16, __half, wmma::col_major> bf[2];
            #pragma unroll
            for (int j = 0; j < 2; j++)
                wmma::load_matrix_sync(bf[j], sB + (warp_n + j * 16) * ROWH + s * 16, ROWH);
            #pragma unroll
            for (int i = 0; i < 4; i++) {
                wmma::fragment<wmma::matrix_a, 16, 16, 16, __half, wmma::row_major> af;
                wmma::load_matrix_sync(af, sA + (warp_m + i * 16) * ROWH + s * 16, ROWH);
                #pragma unroll
                for (int j = 0; j < 2; j++)
                    wmma::mma_sync(acc[i][j], af, bf[j], acc[i][j]);
            }
        }
        __syncthreads();
    }

    // ---- epilogue ----
    float* warp_st = (float*)smem + wid * 256;     // per-warp staging (smem free now)
    if (nb == 3) {
        if (row0 + 128 <= MROWS) {
            #pragma unroll
            for (int i = 0; i < 4; i++)
                #pragma unroll
                for (int j = 0; j < 2; j++)
                    wmma::store_matrix_sync(outp + (size_t)(row0 + warp_m + i * 16) * DDIM
                                                 + warp_n + j * 16,
                                            acc[i][j], DDIM, wmma::mem_row_major);
        } else {
            #pragma unroll
            for (int i = 0; i < 4; i++)
                #pragma unroll
                for (int j = 0; j < 2; j++) {
                    wmma::store_matrix_sync(warp_st, acc[i][j], 16, wmma::mem_row_major);
                    __syncwarp();
                    int r  = lane >> 1;
                    int cc = (lane & 1) * 8;
                    int gr = row0 + warp_m + i * 16 + r;
                    if (gr < MROWS) {
                        #pragma unroll
                        for (int q = 0; q < 8; q++)
                            outp[(size_t)gr * DDIM + warp_n + j * 16 + cc + q] = warp_st[r * 16 + cc + q];
                    }
                    __syncwarp();
                }
        }
    } else {
        // fw block: convert to fp16 via smem staging
        __half* fbase = g_fw + (size_t)nb * MROWS * DDIM;
        #pragma unroll
        for (int i = 0; i < 4; i++)
            #pragma unroll
            for (int j = 0; j < 2; j++) {
                wmma::store_matrix_sync(warp_st, acc[i][j], 16, wmma::mem_row_major);
                __syncwarp();
                int r  = lane >> 1;
                int cc = (lane & 1) * 8;
                int gr = row0 + warp_m + i * 16 + r;
                if (gr < MROWS) {
                    __half tmp[8];
                    #pragma unroll
                    for (int q = 0; q < 8; q++)
                        tmp[q] = __float2half_rn(warp_st[r * 16 + cc + q]);
                    *(uint4*)(fbase + (size_t)gr * DDIM + warp_n + j * 16 + cc) = *(uint4*)tmp;
                }
                __syncwarp();
            }
    }
}

// ---------------------------------------------------------------------------
// CSR build: zero -> histogram -> scan(3 kernels) -> scatter {col,val}
// ---------------------------------------------------------------------------
__global__ void zero_kernel()
{
    int i = blockIdx.x * blockDim.x + threadIdx.x;
    if (i < NHOP * MROWS) g_cur[i] = 0;
}

__global__ void hist_kernel(const int* __restrict__ erow)
{
    int idx = blockIdx.x * blockDim.x + threadIdx.x;
    if (idx >= NHOP * NE) return;
    int hop = idx / NE;
    int r   = erow[idx];
    atomicAdd(&g_cur[hop * MROWS + r], 1);
}

__global__ void scan1_kernel()
{
    int hop = blockIdx.y;
    int i   = blockIdx.x * 1024 + threadIdx.x;
    int tid = threadIdx.x;
    int lane = tid & 31, wid = tid >> 5;

    int v = (i < MROWS) ? g_cur[hop * MROWS + i] : 0;
    int s = v;
    #pragma unroll
    for (int d = 1; d < 32; d <<= 1) {
        int t = __shfl_up_sync(0xffffffffu, s, d);
        if (lane >= d) s += t;
    }
    __shared__ int wsum[32];
    if (lane == 31) wsum[wid] = s;
    __syncthreads();
    if (wid == 0) {
        int ws = wsum[lane];
        #pragma unroll
        for (int d = 1; d < 32; d <<= 1) {
            int t = __shfl_up_sync(0xffffffffu, ws, d);
            if (lane >= d) ws += t;
        }
        wsum[lane] = ws;
    }
    __syncthreads();
    int base = (wid > 0) ? wsum[wid - 1] : 0;
    int incl = base + s;
    if (i < MROWS) g_rowptr[hop * MROWS + i] = incl - v;
    if (tid == 1023) g_aux[hop * 128 + blockIdx.x] = incl;
}

__global__ void scan2_kernel()
{
    int t = threadIdx.x;
    if (t < NHOP) {
        int s = 0;
        for (int k = 0; k < SCANB; k++) {
            int v = g_aux[t * 128 + k];
            g_aux[t * 128 + k] = s;
            s += v;
        }
    }
}

__global__ void scan3_kernel()
{
    int hop = blockIdx.y;
    int i   = blockIdx.x * 1024 + threadIdx.x;
    if (i < MROWS) {
        int v = g_rowptr[hop * MROWS + i] + g_aux[hop * 128 + blockIdx.x];
        g_rowptr[hop * MROWS + i] = v;
        g_cur[hop * MROWS + i]    = v;
    }
}

__global__ void scatter_kernel(const int* __restrict__ erow,
                               const int* __restrict__ ecol,
                               const float* __restrict__ eval)
{
    int idx = blockIdx.x * blockDim.x + threadIdx.x;
    if (idx >= NHOP * NE) return;
    int hop = idx / NE;
    int r   = erow[idx];
    int pos = atomicAdd(&g_cur[hop * MROWS + r], 1);
    g_ecv[(size_t)hop * NE + pos] = make_int2(ecol[idx], __float_as_int(eval[idx]));
}

// ---------------------------------------------------------------------------
// Gather SpMM + relu fused: fp16 fw, fp32 accumulate.
// ---------------------------------------------------------------------------
__global__ void __launch_bounds__(256)
gather_kernel(float* __restrict__ outp)
{
    int gw   = (int)((blockIdx.x * (size_t)blockDim.x + threadIdx.x) >> 5);
    int lane = threadIdx.x & 31;
    if (gw >= MROWS) return;

    float4 acc = make_float4(0.f, 0.f, 0.f, 0.f);

    #pragma unroll
    for (int hop = 0; hop < NHOP; hop++) {
        int start = g_rowptr[hop * MROWS + gw];
        int end   = (gw == MROWS - 1) ? NE : g_rowptr[hop * MROWS + gw + 1];
        const int2*   ecv = g_ecv + (size_t)hop * NE;
        const __half* fw  = g_fw  + (size_t)hop * MROWS * DDIM;

        for (int b = start; b < end; b += 32) {
            int n = end - b;
            if (n > 32) n = 32;
            int c = 0; float v = 0.f;
            if (lane < n) {
                int2 t = ecv[b + lane];
                c = t.x;
                v = __int_as_float(t.y);
            }
            int c0 = __shfl_sync(0xffffffffu, c, 0);
            uint2 raw = *(const uint2*)(fw + (size_t)c0 * DDIM + lane * 4);
            for (int j = 0; j < n; j++) {
                uint2 rawn;
                if (j + 1 < n) {
                    int cn = __shfl_sync(0xffffffffu, c, j + 1);
                    rawn = *(const uint2*)(fw + (size_t)cn * DDIM + lane * 4);
                }
                float vv = __shfl_sync(0xffffffffu, v, j);
                float2 f0 = __half22float2(*(__half2*)&raw.x);
                float2 f1 = __half22float2(*(__half2*)&raw.y);
                acc.x += vv * f0.x;
                acc.y += vv * f0.y;
                acc.z += vv * f1.x;
                acc.w += vv * f1.y;
                raw = rawn;
            }
        }
    }

    float* dst = outp + (size_t)gw * DDIM + lane * 4;
    float4 o = *(float4*)dst;
    o.x = fmaxf(o.x + acc.x, 0.f);
    o.y = fmaxf(o.y + acc.y, 0.f);
    o.z = fmaxf(o.z + acc.z, 0.f);
    o.w = fmaxf(o.w + acc.w, 0.f);
    *(float4*)dst = o;
}

// ---------------------------------------------------------------------------
extern "C" void kernel_launch(void* const* d_in, const int* in_sizes, int n_in,
                              void* d_out, int out_size)
{
    const float* X       = (const float*)d_in[0];
    const int*   erow    = (const int*)  d_in[1];
    const int*   ecol    = (const int*)  d_in[2];
    const float* eval    = (const float*)d_in[3];
    const float* W_embed = (const float*)d_in[4];
    const float* W_feat  = (const float*)d_in[5];
    const float* W_embK  = (const float*)d_in[6];
    const float* alpha   = (const float*)d_in[7];
    float* outp = (float*)d_out;

    (void)in_sizes; (void)n_in; (void)out_size;

    // mm_kernel stays at capture index 3 for the ncu sampler.
    const size_t conv4 = (size_t)MROWS * FDIM / 4;
    convert_kernel<<<(int)((conv4 + 255) / 256), 256>>>(X);          // 0
    fold_kernel<<<256, 512>>>(W_embed, W_feat, W_embK, alpha);       // 1
    zero_kernel<<<(NHOP * MROWS + 255) / 256, 256>>>();              // 2

    static const int smem_bytes = 2 * STAGE_B;   // 40960
    cudaFuncSetAttribute(mm_kernel, cudaFuncAttributeMaxDynamicSharedMemorySize, smem_bytes);
    mm_kernel<<<dim3(4, MB), 256, smem_bytes>>>(outp);               // 3

    hist_kernel<<<(NHOP * NE + 255) / 256, 256>>>(erow);             // 4
    scan1_kernel<<<dim3(SCANB, NHOP), 1024>>>();                     // 5
    scan2_kernel<<<1, 32>>>();                                       // 6
    scan3_kernel<<<dim3(SCANB, NHOP), 1024>>>();                     // 7
    scatter_kernel<<<(NHOP * NE + 255) / 256, 256>>>(erow, ecol, eval); // 8

    gather_kernel<<<(MROWS * 32 + 255) / 256, 256>>>(outp);          // 9
}

// round 16
// speedup vs baseline: 1.0344x; 1.0344x over previous
#include <cuda_runtime.h>
#include <cuda_fp16.h>
#include <mma.h>
#include <cstdint>

using namespace nvcuda;

// Problem constants
#define MROWS 100000
#define FDIM  256
#define DDIM  128
#define NHOP  3
#define NE    1600000
#define NCOLS 512              // 3*128 fw blocks + 128 baseline block
#define MB    782              // ceil(100000/128)
#define SCANB 98               // ceil(100000/1024)

// ---------------------------------------------------------------------------
// Device scratch
// ---------------------------------------------------------------------------
__device__ __half  g_fw[(size_t)NHOP * MROWS * DDIM];   // per-hop fw (fp16)
__device__ __half  g_Xf[(size_t)MROWS * FDIM];          // X fp16
__device__ __half  g_Wtf[(size_t)NCOLS * FDIM];         // Wcomb^T fp16 [512][256]
__device__ int     g_rowptr[NHOP * MROWS];
__device__ int     g_cur[NHOP * MROWS];
__device__ int     g_aux[NHOP * 128];
__device__ int2    g_ecv[(size_t)NHOP * NE];            // CSR-ordered {col, val}

__device__ __forceinline__ uint32_t smem_u32(const void* p) {
    uint32_t a;
    asm("{ .reg .u64 t; cvta.to.shared.u64 t, %1; cvt.u32.u64 %0, t; }" : "=r"(a) : "l"(p));
    return a;
}
__device__ __forceinline__ void cp16(uint32_t dst, const void* src, int src_sz) {
    asm volatile("cp.async.ca.shared.global [%0], [%1], 16, %2;"
                 :: "r"(dst), "l"(src), "r"(src_sz) : "memory");
}

// ---------------------------------------------------------------------------
// Convert X (fp32) -> fp16
// ---------------------------------------------------------------------------
__global__ void convert_kernel(const float* __restrict__ X)
{
    size_t i = (size_t)blockIdx.x * blockDim.x + threadIdx.x;
    const size_t total4 = (size_t)MROWS * FDIM / 4;
    if (i >= total4) return;
    float4 v = ((const float4*)X)[i];
    __half2 a = __floats2half2_rn(v.x, v.y);
    __half2 b = __floats2half2_rn(v.z, v.w);
    ((uint2*)g_Xf)[i] = make_uint2(*(uint32_t*)&a, *(uint32_t*)&b);
}

// ---------------------------------------------------------------------------
// Fold kernel: build Wcomb^T in fp16.  grid=256 (k), block=512 (j)
// ---------------------------------------------------------------------------
__global__ void fold_kernel(const float* __restrict__ W_embed,
                            const float* __restrict__ W_feat,
                            const float* __restrict__ W_embK,
                            const float* __restrict__ alpha_p)
{
    int k = blockIdx.x;
    int j = threadIdx.x;
    float r;
    if (j < 3 * DDIM) {
        int hop = j >> 7;
        int jj  = j & 127;
        r = W_feat[((size_t)hop * FDIM + k) * DDIM + jj];
    } else {
        int jj = j - 3 * DDIM;
        float s = 0.f;
        #pragma unroll 4
        for (int d = 0; d < DDIM; d++) {
            float wc = W_embK[d * DDIM + jj]
                     + W_embK[DDIM * DDIM + d * DDIM + jj]
                     + W_embK[2 * DDIM * DDIM + d * DDIM + jj];
            s += W_embed[k * DDIM + d] * wc;
        }
        r = alpha_p[0] * s;
    }
    g_Wtf[(size_t)j * FDIM + k] = __float2half_rn(r);
}

// ---------------------------------------------------------------------------
// Single-pass fp16 wmma GEMM with cp.async double buffering (unchanged R15).
// ---------------------------------------------------------------------------
#define ROWH    40
#define TILE_H  (128 * ROWH)
#define STAGE_H (2 * TILE_H)
#define STAGE_B (STAGE_H * 2)            // 20480 bytes
#define NKC     8

__global__ void __launch_bounds__(256, 3)
mm_kernel(float* __restrict__ outp)
{
    extern __shared__ __align__(32) __half smem[];
    const uint32_t sb = smem_u32(smem);

    int tid  = threadIdx.x;
    int wid  = tid >> 5;
    int lane = tid & 31;
    int nb   = blockIdx.x;
    int mb   = blockIdx.y;
    int row0 = mb * 128;
    int n0   = nb * 128;
    int warp_m = (wid & 1) * 64;
    int warp_n = (wid >> 1) * 32;

    auto issue_stage = [&](int kc, int stage) {
        const int k0 = kc * 32;
        const uint32_t s0 = sb + stage * STAGE_B;
        #pragma unroll
        for (int t = 0; t < 2; t++) {
            int c   = tid + 256 * t;
            int row = c >> 2;
            int c4  = c & 3;
            uint32_t doff = (uint32_t)(row * ROWH + c4 * 8) * 2;
            int gr = row0 + row;
            int ok = (gr < MROWS) ? 16 : 0;
            cp16(s0 + doff, g_Xf + (size_t)gr * FDIM + k0 + c4 * 8, ok);
            cp16(s0 + TILE_H * 2 + doff, g_Wtf + (size_t)(n0 + row) * FDIM + k0 + c4 * 8, 16);
        }
        asm volatile("cp.async.commit_group;" ::: "memory");
    };

    wmma::fragment<wmma::accumulator, 16, 16, 16, float> acc[4][2];
    #pragma unroll
    for (int i = 0; i < 4; i++)
        #pragma unroll
        for (int j = 0; j < 2; j++)
            wmma::fill_fragment(acc[i][j], 0.f);

    issue_stage(0, 0);

    for (int kc = 0; kc < NKC; kc++) {
        int stage = kc & 1;
        if (kc + 1 < NKC) {
            issue_stage(kc + 1, stage ^ 1);
            asm volatile("cp.async.wait_group 1;" ::: "memory");
        } else {
            asm volatile("cp.async.wait_group 0;" ::: "memory");
        }
        __syncthreads();

        __half* sA = smem + stage * STAGE_H;
        __half* sB = sA + TILE_H;

        #pragma unroll
        for (int s = 0; s < 2; s++) {
            wmma::fragment<wmma::matrix_b, 16, 16, 16, __half, wmma::col_major> bf[2];
            #pragma unroll
            for (int j = 0; j < 2; j++)
                wmma::load_matrix_sync(bf[j], sB + (warp_n + j * 16) * ROWH + s * 16, ROWH);
            #pragma unroll
            for (int i = 0; i < 4; i++) {
                wmma::fragment<wmma::matrix_a, 16, 16, 16, __half, wmma::row_major> af;
                wmma::load_matrix_sync(af, sA + (warp_m + i * 16) * ROWH + s * 16, ROWH);
                #pragma unroll
                for (int j = 0; j < 2; j++)
                    wmma::mma_sync(acc[i][j], af, bf[j], acc[i][j]);
            }
        }
        __syncthreads();
    }

    // ---- epilogue ----
    float* warp_st = (float*)smem + wid * 256;
    if (nb == 3) {
        if (row0 + 128 <= MROWS) {
            #pragma unroll
            for (int i = 0; i < 4; i++)
                #pragma unroll
                for (int j = 0; j < 2; j++)
                    wmma::store_matrix_sync(outp + (size_t)(row0 + warp_m + i * 16) * DDIM
                                                 + warp_n + j * 16,
                                            acc[i][j], DDIM, wmma::mem_row_major);
        } else {
            #pragma unroll
            for (int i = 0; i < 4; i++)
                #pragma unroll
                for (int j = 0; j < 2; j++) {
                    wmma::store_matrix_sync(warp_st, acc[i][j], 16, wmma::mem_row_major);
                    __syncwarp();
                    int r  = lane >> 1;
                    int cc = (lane & 1) * 8;
                    int gr = row0 + warp_m + i * 16 + r;
                    if (gr < MROWS) {
                        #pragma unroll
                        for (int q = 0; q < 8; q++)
                            outp[(size_t)gr * DDIM + warp_n + j * 16 + cc + q] = warp_st[r * 16 + cc + q];
                    }
                    __syncwarp();
                }
        }
    } else {
        __half* fbase = g_fw + (size_t)nb * MROWS * DDIM;
        #pragma unroll
        for (int i = 0; i < 4; i++)
            #pragma unroll
            for (int j = 0; j < 2; j++) {
                wmma::store_matrix_sync(warp_st, acc[i][j], 16, wmma::mem_row_major);
                __syncwarp();
                int r  = lane >> 1;
                int cc = (lane & 1) * 8;
                int gr = row0 + warp_m + i * 16 + r;
                if (gr < MROWS) {
                    __half tmp[8];
                    #pragma unroll
                    for (int q = 0; q < 8; q++)
                        tmp[q] = __float2half_rn(warp_st[r * 16 + cc + q]);
                    *(uint4*)(fbase + (size_t)gr * DDIM + warp_n + j * 16 + cc) = *(uint4*)tmp;
                }
                __syncwarp();
            }
    }
}

// ---------------------------------------------------------------------------
// CSR build: zero -> histogram -> scan(3 kernels) -> scatter {col,val}
// ---------------------------------------------------------------------------
__global__ void zero_kernel()
{
    int i = blockIdx.x * blockDim.x + threadIdx.x;
    if (i < NHOP * MROWS) g_cur[i] = 0;
}

__global__ void hist_kernel(const int* __restrict__ erow)
{
    int idx = blockIdx.x * blockDim.x + threadIdx.x;
    if (idx >= NHOP * NE) return;
    int hop = idx / NE;
    int r   = erow[idx];
    atomicAdd(&g_cur[hop * MROWS + r], 1);
}

__global__ void scan1_kernel()
{
    int hop = blockIdx.y;
    int i   = blockIdx.x * 1024 + threadIdx.x;
    int tid = threadIdx.x;
    int lane = tid & 31, wid = tid >> 5;

    int v = (i < MROWS) ? g_cur[hop * MROWS + i] : 0;
    int s = v;
    #pragma unroll
    for (int d = 1; d < 32; d <<= 1) {
        int t = __shfl_up_sync(0xffffffffu, s, d);
        if (lane >= d) s += t;
    }
    __shared__ int wsum[32];
    if (lane == 31) wsum[wid] = s;
    __syncthreads();
    if (wid == 0) {
        int ws = wsum[lane];
        #pragma unroll
        for (int d = 1; d < 32; d <<= 1) {
            int t = __shfl_up_sync(0xffffffffu, ws, d);
            if (lane >= d) ws += t;
        }
        wsum[lane] = ws;
    }
    __syncthreads();
    int base = (wid > 0) ? wsum[wid - 1] : 0;
    int incl = base + s;
    if (i < MROWS) g_rowptr[hop * MROWS + i] = incl - v;
    if (tid == 1023) g_aux[hop * 128 + blockIdx.x] = incl;
}

__global__ void scan2_kernel()
{
    int t = threadIdx.x;
    if (t < NHOP) {
        int s = 0;
        for (int k = 0; k < SCANB; k++) {
            int v = g_aux[t * 128 + k];
            g_aux[t * 128 + k] = s;
            s += v;
        }
    }
}

__global__ void scan3_kernel()
{
    int hop = blockIdx.y;
    int i   = blockIdx.x * 1024 + threadIdx.x;
    if (i < MROWS) {
        int v = g_rowptr[hop * MROWS + i] + g_aux[hop * 128 + blockIdx.x];
        g_rowptr[hop * MROWS + i] = v;
        g_cur[hop * MROWS + i]    = v;
    }
}

__global__ void scatter_kernel(const int* __restrict__ erow,
                               const int* __restrict__ ecol,
                               const float* __restrict__ eval)
{
    int idx = blockIdx.x * blockDim.x + threadIdx.x;
    if (idx >= NHOP * NE) return;
    int hop = idx / NE;
    int r   = erow[idx];
    int pos = atomicAdd(&g_cur[hop * MROWS + r], 1);
    g_ecv[(size_t)hop * NE + pos] = make_int2(ecol[idx], __float_as_int(eval[idx]));
}

// ---------------------------------------------------------------------------
// Gather SpMM + relu fused: fp16 fw, fp32 accumulate.
// ---------------------------------------------------------------------------
__global__ void __launch_bounds__(256)
gather_kernel(float* __restrict__ outp)
{
    int gw   = (int)((blockIdx.x * (size_t)blockDim.x + threadIdx.x) >> 5);
    int lane = threadIdx.x & 31;
    if (gw >= MROWS) return;

    float4 acc = make_float4(0.f, 0.f, 0.f, 0.f);

    #pragma unroll
    for (int hop = 0; hop < NHOP; hop++) {
        int start = g_rowptr[hop * MROWS + gw];
        int end   = (gw == MROWS - 1) ? NE : g_rowptr[hop * MROWS + gw + 1];
        const int2*   ecv = g_ecv + (size_t)hop * NE;
        const __half* fw  = g_fw  + (size_t)hop * MROWS * DDIM;

        for (int b = start; b < end; b += 32) {
            int n = end - b;
            if (n > 32) n = 32;
            int c = 0; float v = 0.f;
            if (lane < n) {
                int2 t = ecv[b + lane];
                c = t.x;
                v = __int_as_float(t.y);
            }
            int c0 = __shfl_sync(0xffffffffu, c, 0);
            uint2 raw = *(const uint2*)(fw + (size_t)c0 * DDIM + lane * 4);
            for (int j = 0; j < n; j++) {
                uint2 rawn;
                if (j + 1 < n) {
                    int cn = __shfl_sync(0xffffffffu, c, j + 1);
                    rawn = *(const uint2*)(fw + (size_t)cn * DDIM + lane * 4);
                }
                float vv = __shfl_sync(0xffffffffu, v, j);
                float2 f0 = __half22float2(*(__half2*)&raw.x);
                float2 f1 = __half22float2(*(__half2*)&raw.y);
                acc.x += vv * f0.x;
                acc.y += vv * f0.y;
                acc.z += vv * f1.x;
                acc.w += vv * f1.y;
                raw = rawn;
            }
        }
    }

    float* dst = outp + (size_t)gw * DDIM + lane * 4;
    float4 o = *(float4*)dst;
    o.x = fmaxf(o.x + acc.x, 0.f);
    o.y = fmaxf(o.y + acc.y, 0.f);
    o.z = fmaxf(o.z + acc.z, 0.f);
    o.w = fmaxf(o.w + acc.w, 0.f);
    *(float4*)dst = o;
}

// ---------------------------------------------------------------------------
// Launch: CSR build forked onto a second stream, overlapped with the dense
// path (convert/fold/mm). Event fork/join is graph-capture legal. Stream &
// events are host-side objects created on the first (uncaptured) call; the
// GPU work per call is identical every time.
// ---------------------------------------------------------------------------
extern "C" void kernel_launch(void* const* d_in, const int* in_sizes, int n_in,
                              void* d_out, int out_size)
{
    const float* X       = (const float*)d_in[0];
    const int*   erow    = (const int*)  d_in[1];
    const int*   ecol    = (const int*)  d_in[2];
    const float* eval    = (const float*)d_in[3];
    const float* W_embed = (const float*)d_in[4];
    const float* W_feat  = (const float*)d_in[5];
    const float* W_embK  = (const float*)d_in[6];
    const float* alpha   = (const float*)d_in[7];
    float* outp = (float*)d_out;

    (void)in_sizes; (void)n_in; (void)out_size;

    static cudaStream_t s2 = nullptr;
    static cudaEvent_t  evFork = nullptr, evJoin = nullptr;
    if (s2 == nullptr) {
        cudaStreamCreateWithFlags(&s2, cudaStreamNonBlocking);
        cudaEventCreateWithFlags(&evFork, cudaEventDisableTiming);
        cudaEventCreateWithFlags(&evJoin, cudaEventDisableTiming);
    }
    const cudaStream_t s1 = (cudaStream_t)0;   // legacy default (capture) stream

    // Fork: CSR branch waits on nothing prior in s1 except capture start.
    cudaEventRecord(evFork, s1);
    cudaStreamWaitEvent(s2, evFork, 0);

    // ---- dense branch (s1) + CSR branch (s2), issued interleaved so that
    //      mm_kernel stays at kernel-launch index 3 for the ncu sampler ----
    const size_t conv4 = (size_t)MROWS * FDIM / 4;
    convert_kernel<<<(int)((conv4 + 255) / 256), 256, 0, s1>>>(X);           // 0
    fold_kernel<<<256, 512, 0, s1>>>(W_embed, W_feat, W_embK, alpha);        // 1
    zero_kernel<<<(NHOP * MROWS + 255) / 256, 256, 0, s2>>>();               // 2

    static const int smem_bytes = 2 * STAGE_B;   // 40960
    cudaFuncSetAttribute(mm_kernel, cudaFuncAttributeMaxDynamicSharedMemorySize, smem_bytes);
    mm_kernel<<<dim3(4, MB), 256, smem_bytes, s1>>>(outp);                   // 3

    hist_kernel<<<(NHOP * NE + 255) / 256, 256, 0, s2>>>(erow);              // 4
    scan1_kernel<<<dim3(SCANB, NHOP), 1024, 0, s2>>>();                      // 5
    scan2_kernel<<<1, 32, 0, s2>>>();                                        // 6
    scan3_kernel<<<dim3(SCANB, NHOP), 1024, 0, s2>>>();                      // 7
    scatter_kernel<<<(NHOP * NE + 255) / 256, 256, 0, s2>>>(erow, ecol, eval); // 8

    // Join: gather needs both g_fw (s1/mm) and CSR (s2).
    cudaEventRecord(evJoin, s2);
    cudaStreamWaitEvent(s1, evJoin, 0);

    gather_kernel<<<(MROWS * 32 + 255) / 256, 256, 0, s1>>>(outp);           // 9
}

// round 17
// speedup vs baseline: 1.0355x; 1.0011x over previous
#include <cuda_runtime.h>
#include <cuda_fp16.h>
#include <mma.h>
#include <cstdint>

using namespace nvcuda;

// Problem constants
#define MROWS 100000
#define FDIM  256
#define DDIM  128
#define NHOP  3
#define NE    1600000
#define NCOLS 512              // 3*128 fw blocks + 128 baseline block
#define MB    782              // ceil(100000/128)
#define SCANB 98               // ceil(100000/1024)

// ---------------------------------------------------------------------------
// Device scratch
// ---------------------------------------------------------------------------
__device__ __half  g_fw[(size_t)NHOP * MROWS * DDIM];   // per-hop fw (fp16)
__device__ __half  g_Xf[(size_t)MROWS * FDIM];          // X fp16
__device__ __half  g_Wtf[(size_t)NCOLS * FDIM];         // Wcomb^T fp16 [512][256]
__device__ int     g_rowptr[NHOP * MROWS];
__device__ int     g_cur[NHOP * MROWS];
__device__ int     g_aux[NHOP * 128];
__device__ int2    g_ecv[(size_t)NHOP * NE];            // CSR-ordered {col, val}

__device__ __forceinline__ uint32_t smem_u32(const void* p) {
    uint32_t a;
    asm("{ .reg .u64 t; cvta.to.shared.u64 t, %1; cvt.u32.u64 %0, t; }" : "=r"(a) : "l"(p));
    return a;
}
__device__ __forceinline__ void cp16(uint32_t dst, const void* src, int src_sz) {
    asm volatile("cp.async.ca.shared.global [%0], [%1], 16, %2;"
                 :: "r"(dst), "l"(src), "r"(src_sz) : "memory");
}

// ---------------------------------------------------------------------------
// Convert X (fp32) -> fp16
// ---------------------------------------------------------------------------
__global__ void convert_kernel(const float* __restrict__ X)
{
    size_t i = (size_t)blockIdx.x * blockDim.x + threadIdx.x;
    const size_t total4 = (size_t)MROWS * FDIM / 4;
    if (i >= total4) return;
    float4 v = ((const float4*)X)[i];
    __half2 a = __floats2half2_rn(v.x, v.y);
    __half2 b = __floats2half2_rn(v.z, v.w);
    ((uint2*)g_Xf)[i] = make_uint2(*(uint32_t*)&a, *(uint32_t*)&b);
}

// ---------------------------------------------------------------------------
// Fold kernel: build Wcomb^T in fp16.  grid=256 (k), block=512 (j)
// ---------------------------------------------------------------------------
__global__ void fold_kernel(const float* __restrict__ W_embed,
                            const float* __restrict__ W_feat,
                            const float* __restrict__ W_embK,
                            const float* __restrict__ alpha_p)
{
    int k = blockIdx.x;
    int j = threadIdx.x;
    float r;
    if (j < 3 * DDIM) {
        int hop = j >> 7;
        int jj  = j & 127;
        r = W_feat[((size_t)hop * FDIM + k) * DDIM + jj];
    } else {
        int jj = j - 3 * DDIM;
        float s = 0.f;
        #pragma unroll 4
        for (int d = 0; d < DDIM; d++) {
            float wc = W_embK[d * DDIM + jj]
                     + W_embK[DDIM * DDIM + d * DDIM + jj]
                     + W_embK[2 * DDIM * DDIM + d * DDIM + jj];
            s += W_embed[k * DDIM + d] * wc;
        }
        r = alpha_p[0] * s;
    }
    g_Wtf[(size_t)j * FDIM + k] = __float2half_rn(r);
}

// ---------------------------------------------------------------------------
// Single-pass fp16 wmma GEMM with cp.async double buffering (unchanged).
// ---------------------------------------------------------------------------
#define ROWH    40
#define TILE_H  (128 * ROWH)
#define STAGE_H (2 * TILE_H)
#define STAGE_B (STAGE_H * 2)            // 20480 bytes
#define NKC     8

__global__ void __launch_bounds__(256, 3)
mm_kernel(float* __restrict__ outp)
{
    extern __shared__ __align__(32) __half smem[];
    const uint32_t sb = smem_u32(smem);

    int tid  = threadIdx.x;
    int wid  = tid >> 5;
    int lane = tid & 31;
    int nb   = blockIdx.x;
    int mb   = blockIdx.y;
    int row0 = mb * 128;
    int n0   = nb * 128;
    int warp_m = (wid & 1) * 64;
    int warp_n = (wid >> 1) * 32;

    auto issue_stage = [&](int kc, int stage) {
        const int k0 = kc * 32;
        const uint32_t s0 = sb + stage * STAGE_B;
        #pragma unroll
        for (int t = 0; t < 2; t++) {
            int c   = tid + 256 * t;
            int row = c >> 2;
            int c4  = c & 3;
            uint32_t doff = (uint32_t)(row * ROWH + c4 * 8) * 2;
            int gr = row0 + row;
            int ok = (gr < MROWS) ? 16 : 0;
            cp16(s0 + doff, g_Xf + (size_t)gr * FDIM + k0 + c4 * 8, ok);
            cp16(s0 + TILE_H * 2 + doff, g_Wtf + (size_t)(n0 + row) * FDIM + k0 + c4 * 8, 16);
        }
        asm volatile("cp.async.commit_group;" ::: "memory");
    };

    wmma::fragment<wmma::accumulator, 16, 16, 16, float> acc[4][2];
    #pragma unroll
    for (int i = 0; i < 4; i++)
        #pragma unroll
        for (int j = 0; j < 2; j++)
            wmma::fill_fragment(acc[i][j], 0.f);

    issue_stage(0, 0);

    for (int kc = 0; kc < NKC; kc++) {
        int stage = kc & 1;
        if (kc + 1 < NKC) {
            issue_stage(kc + 1, stage ^ 1);
            asm volatile("cp.async.wait_group 1;" ::: "memory");
        } else {
            asm volatile("cp.async.wait_group 0;" ::: "memory");
        }
        __syncthreads();

        __half* sA = smem + stage * STAGE_H;
        __half* sB = sA + TILE_H;

        #pragma unroll
        for (int s = 0; s < 2; s++) {
            wmma::fragment<wmma::matrix_b, 16, 16, 16, __half, wmma::col_major> bf[2];
            #pragma unroll
            for (int j = 0; j < 2; j++)
                wmma::load_matrix_sync(bf[j], sB + (warp_n + j * 16) * ROWH + s * 16, ROWH);
            #pragma unroll
            for (int i = 0; i < 4; i++) {
                wmma::fragment<wmma::matrix_a, 16, 16, 16, __half, wmma::row_major> af;
                wmma::load_matrix_sync(af, sA + (warp_m + i * 16) * ROWH + s * 16, ROWH);
                #pragma unroll
                for (int j = 0; j < 2; j++)
                    wmma::mma_sync(acc[i][j], af, bf[j], acc[i][j]);
            }
        }
        __syncthreads();
    }

    // ---- epilogue ----
    float* warp_st = (float*)smem + wid * 256;
    if (nb == 3) {
        if (row0 + 128 <= MROWS) {
            #pragma unroll
            for (int i = 0; i < 4; i++)
                #pragma unroll
                for (int j = 0; j < 2; j++)
                    wmma::store_matrix_sync(outp + (size_t)(row0 + warp_m + i * 16) * DDIM
                                                 + warp_n + j * 16,
                                            acc[i][j], DDIM, wmma::mem_row_major);
        } else {
            #pragma unroll
            for (int i = 0; i < 4; i++)
                #pragma unroll
                for (int j = 0; j < 2; j++) {
                    wmma::store_matrix_sync(warp_st, acc[i][j], 16, wmma::mem_row_major);
                    __syncwarp();
                    int r  = lane >> 1;
                    int cc = (lane & 1) * 8;
                    int gr = row0 + warp_m + i * 16 + r;
                    if (gr < MROWS) {
                        #pragma unroll
                        for (int q = 0; q < 8; q++)
                            outp[(size_t)gr * DDIM + warp_n + j * 16 + cc + q] = warp_st[r * 16 + cc + q];
                    }
                    __syncwarp();
                }
        }
    } else {
        __half* fbase = g_fw + (size_t)nb * MROWS * DDIM;
        #pragma unroll
        for (int i = 0; i < 4; i++)
            #pragma unroll
            for (int j = 0; j < 2; j++) {
                wmma::store_matrix_sync(warp_st, acc[i][j], 16, wmma::mem_row_major);
                __syncwarp();
                int r  = lane >> 1;
                int cc = (lane & 1) * 8;
                int gr = row0 + warp_m + i * 16 + r;
                if (gr < MROWS) {
                    __half tmp[8];
                    #pragma unroll
                    for (int q = 0; q < 8; q++)
                        tmp[q] = __float2half_rn(warp_st[r * 16 + cc + q]);
                    *(uint4*)(fbase + (size_t)gr * DDIM + warp_n + j * 16 + cc) = *(uint4*)tmp;
                }
                __syncwarp();
            }
    }
}

// ---------------------------------------------------------------------------
// CSR build: zero -> histogram -> scan(3 kernels) -> scatter {col,val}
// ---------------------------------------------------------------------------
__global__ void zero_kernel()
{
    int i = blockIdx.x * blockDim.x + threadIdx.x;
    if (i < NHOP * MROWS) g_cur[i] = 0;
}

__global__ void hist_kernel(const int* __restrict__ erow)
{
    int idx = blockIdx.x * blockDim.x + threadIdx.x;
    if (idx >= NHOP * NE) return;
    int hop = idx / NE;
    int r   = erow[idx];
    atomicAdd(&g_cur[hop * MROWS + r], 1);
}

__global__ void scan1_kernel()
{
    int hop = blockIdx.y;
    int i   = blockIdx.x * 1024 + threadIdx.x;
    int tid = threadIdx.x;
    int lane = tid & 31, wid = tid >> 5;

    int v = (i < MROWS) ? g_cur[hop * MROWS + i] : 0;
    int s = v;
    #pragma unroll
    for (int d = 1; d < 32; d <<= 1) {
        int t = __shfl_up_sync(0xffffffffu, s, d);
        if (lane >= d) s += t;
    }
    __shared__ int wsum[32];
    if (lane == 31) wsum[wid] = s;
    __syncthreads();
    if (wid == 0) {
        int ws = wsum[lane];
        #pragma unroll
        for (int d = 1; d < 32; d <<= 1) {
            int t = __shfl_up_sync(0xffffffffu, ws, d);
            if (lane >= d) ws += t;
        }
        wsum[lane] = ws;
    }
    __syncthreads();
    int base = (wid > 0) ? wsum[wid - 1] : 0;
    int incl = base + s;
    if (i < MROWS) g_rowptr[hop * MROWS + i] = incl - v;
    if (tid == 1023) g_aux[hop * 128 + blockIdx.x] = incl;
}

__global__ void scan2_kernel()
{
    int t = threadIdx.x;
    if (t < NHOP) {
        int s = 0;
        for (int k = 0; k < SCANB; k++) {
            int v = g_aux[t * 128 + k];
            g_aux[t * 128 + k] = s;
            s += v;
        }
    }
}

__global__ void scan3_kernel()
{
    int hop = blockIdx.y;
    int i   = blockIdx.x * 1024 + threadIdx.x;
    if (i < MROWS) {
        int v = g_rowptr[hop * MROWS + i] + g_aux[hop * 128 + blockIdx.x];
        g_rowptr[hop * MROWS + i] = v;
        g_cur[hop * MROWS + i]    = v;
    }
}

__global__ void scatter_kernel(const int* __restrict__ erow,
                               const int* __restrict__ ecol,
                               const float* __restrict__ eval)
{
    int idx = blockIdx.x * blockDim.x + threadIdx.x;
    if (idx >= NHOP * NE) return;
    int hop = idx / NE;
    int r   = erow[idx];
    int pos = atomicAdd(&g_cur[hop * MROWS + r], 1);
    g_ecv[(size_t)hop * NE + pos] = make_int2(ecol[idx], __float_as_int(eval[idx]));
}

// ---------------------------------------------------------------------------
// Gather SpMM + relu fused: fp16 fw, fp32 accumulate.
// ---------------------------------------------------------------------------
__global__ void __launch_bounds__(256)
gather_kernel(float* __restrict__ outp)
{
    int gw   = (int)((blockIdx.x * (size_t)blockDim.x + threadIdx.x) >> 5);
    int lane = threadIdx.x & 31;
    if (gw >= MROWS) return;

    float4 acc = make_float4(0.f, 0.f, 0.f, 0.f);

    #pragma unroll
    for (int hop = 0; hop < NHOP; hop++) {
        int start = g_rowptr[hop * MROWS + gw];
        int end   = (gw == MROWS - 1) ? NE : g_rowptr[hop * MROWS + gw + 1];
        const int2*   ecv = g_ecv + (size_t)hop * NE;
        const __half* fw  = g_fw  + (size_t)hop * MROWS * DDIM;

        for (int b = start; b < end; b += 32) {
            int n = end - b;
            if (n > 32) n = 32;
            int c = 0; float v = 0.f;
            if (lane < n) {
                int2 t = ecv[b + lane];
                c = t.x;
                v = __int_as_float(t.y);
            }
            int c0 = __shfl_sync(0xffffffffu, c, 0);
            uint2 raw = *(const uint2*)(fw + (size_t)c0 * DDIM + lane * 4);
            for (int j = 0; j < n; j++) {
                uint2 rawn;
                if (j + 1 < n) {
                    int cn = __shfl_sync(0xffffffffu, c, j + 1);
                    rawn = *(const uint2*)(fw + (size_t)cn * DDIM + lane * 4);
                }
                float vv = __shfl_sync(0xffffffffu, v, j);
                float2 f0 = __half22float2(*(__half2*)&raw.x);
                float2 f1 = __half22float2(*(__half2*)&raw.y);
                acc.x += vv * f0.x;
                acc.y += vv * f0.y;
                acc.z += vv * f1.x;
                acc.w += vv * f1.y;
                raw = rawn;
            }
        }
    }

    float* dst = outp + (size_t)gw * DDIM + lane * 4;
    float4 o = *(float4*)dst;
    o.x = fmaxf(o.x + acc.x, 0.f);
    o.y = fmaxf(o.y + acc.y, 0.f);
    o.z = fmaxf(o.z + acc.z, 0.f);
    o.w = fmaxf(o.w + acc.w, 0.f);
    *(float4*)dst = o;
}

// ---------------------------------------------------------------------------
// Launch: dense branch and CSR branch BOTH on non-blocking streams (the R16
// attempt put the dense branch on the legacy default stream, whose implicit
// sync semantics serialized the two branches in the captured graph). The
// capture stream only records the fork event and runs the final gather.
// ---------------------------------------------------------------------------
extern "C" void kernel_launch(void* const* d_in, const int* in_sizes, int n_in,
                              void* d_out, int out_size)
{
    const float* X       = (const float*)d_in[0];
    const int*   erow    = (const int*)  d_in[1];
    const int*   ecol    = (const int*)  d_in[2];
    const float* eval    = (const float*)d_in[3];
    const float* W_embed = (const float*)d_in[4];
    const float* W_feat  = (const float*)d_in[5];
    const float* W_embK  = (const float*)d_in[6];
    const float* alpha   = (const float*)d_in[7];
    float* outp = (float*)d_out;

    (void)in_sizes; (void)n_in; (void)out_size;

    static cudaStream_t s1 = nullptr, s2 = nullptr;
    static cudaEvent_t  evFork = nullptr, evJ1 = nullptr, evJ2 = nullptr;
    if (s1 == nullptr) {
        cudaStreamCreateWithFlags(&s1, cudaStreamNonBlocking);
        cudaStreamCreateWithFlags(&s2, cudaStreamNonBlocking);
        cudaEventCreateWithFlags(&evFork, cudaEventDisableTiming);
        cudaEventCreateWithFlags(&evJ1, cudaEventDisableTiming);
        cudaEventCreateWithFlags(&evJ2, cudaEventDisableTiming);
    }
    const cudaStream_t cap = (cudaStream_t)0;   // harness capture stream

    // Fork both branches off the capture stream.
    cudaEventRecord(evFork, cap);
    cudaStreamWaitEvent(s1, evFork, 0);
    cudaStreamWaitEvent(s2, evFork, 0);

    // Interleaved issue order keeps mm_kernel at launch index 3 for ncu.
    const size_t conv4 = (size_t)MROWS * FDIM / 4;
    convert_kernel<<<(int)((conv4 + 255) / 256), 256, 0, s1>>>(X);             // 0
    fold_kernel<<<256, 512, 0, s1>>>(W_embed, W_feat, W_embK, alpha);          // 1
    zero_kernel<<<(NHOP * MROWS + 255) / 256, 256, 0, s2>>>();                 // 2

    static const int smem_bytes = 2 * STAGE_B;   // 40960
    cudaFuncSetAttribute(mm_kernel, cudaFuncAttributeMaxDynamicSharedMemorySize, smem_bytes);
    mm_kernel<<<dim3(4, MB), 256, smem_bytes, s1>>>(outp);                     // 3

    hist_kernel<<<(NHOP * NE + 255) / 256, 256, 0, s2>>>(erow);                // 4
    scan1_kernel<<<dim3(SCANB, NHOP), 1024, 0, s2>>>();                        // 5
    scan2_kernel<<<1, 32, 0, s2>>>();                                          // 6
    scan3_kernel<<<dim3(SCANB, NHOP), 1024, 0, s2>>>();                        // 7
    scatter_kernel<<<(NHOP * NE + 255) / 256, 256, 0, s2>>>(erow, ecol, eval); // 8

    // Join both branches back into the capture stream; gather needs g_fw + CSR.
    cudaEventRecord(evJ1, s1);
    cudaEventRecord(evJ2, s2);
    cudaStreamWaitEvent(cap, evJ1, 0);
    cudaStreamWaitEvent(cap, evJ2, 0);

    gather_kernel<<<(MROWS * 32 + 255) / 256, 256, 0, cap>>>(outp);            // 9
}